// round 1
// baseline (speedup 1.0000x reference)
#include <cuda_runtime.h>
#include <cstdint>
#include <math_constants.h>

// Problem constants (fixed by dataset)
constexpr int C  = 128;   // channels
constexpr int KN = 16;    // knn neighbors
constexpr int NMAX = 100000;

// ---------------- device scratch (no runtime allocation allowed) -------------
__device__ float g_h0[(size_t)NMAX * C];      // f@W_pre + b_pre (pre-BN1)
__device__ float g_pooled[(size_t)NMAX * C];  // max-pooled (pre-BN2)
__device__ float g_t[(size_t)NMAX * C];       // bn2(pooled)@W_f1 + b_f1 (pre-BN3)
__device__ float g_u[(size_t)NMAX * C];       // relu(bn3)@W_f2 + b_f2 (pre-BN4)

__device__ float g_sum[4][C];
__device__ float g_sq[4][C];
__device__ float g_scale[4][C];
__device__ float g_shift[4][C];

// ---------------- tiny kernels ----------------------------------------------
__global__ void zero_stats_kernel() {
    int i = threadIdx.x;
    if (i < C) {
        #pragma unroll
        for (int s = 0; s < 4; s++) { g_sum[s][i] = 0.f; g_sq[s][i] = 0.f; }
    }
}

__global__ void finalize_kernel(int s, const float* __restrict__ gamma,
                                const float* __restrict__ beta, float invN) {
    int c = threadIdx.x;
    float mean = g_sum[s][c] * invN;
    float var  = g_sq[s][c] * invN - mean * mean;
    float sc   = gamma[c] * rsqrtf(var + 1e-5f);
    g_scale[s][c] = sc;
    g_shift[s][c] = beta[c] - mean * sc;
}

// ---------------- GEMM: out[n,c] = sum_k A'[n,k] W[k,c] + b[c] ---------------
// MODE 0: A' = A
// MODE 1: A' = A*scale[stat_in] + shift[stat_in]
// MODE 2: A' = relu(A*scale[stat_in] + shift[stat_in])
// Also accumulates per-column sum / sumsq of 'out' into stats slot stat_out.
// Tile: 64 rows x 128 cols per block, 256 threads, thread tile 8x4.
template <int MODE>
__global__ void gemm_kernel(const float* __restrict__ A,
                            const float* __restrict__ W,
                            const float* __restrict__ bias,
                            float* __restrict__ out,
                            int stat_in, int stat_out, int N) {
    extern __shared__ float smem[];
    float* sW   = smem;               // C*C   = 16384 floats
    float* sA   = sW + C * C;         // 64*C  = 8192 floats
    float* sSum = sA + 64 * C;        // C
    float* sSq  = sSum + C;           // C

    const int tid  = threadIdx.x;     // 256 threads
    const int row0 = blockIdx.x * 64;

    // load W (16384 floats)
    for (int i = tid * 4; i < C * C; i += 256 * 4)
        *(float4*)(sW + i) = *(const float4*)(W + i);

    // load A tile with optional BN transform
    for (int i = tid * 4; i < 64 * C; i += 256 * 4) {
        int r = i >> 7;          // /C
        int c = i & (C - 1);
        float4 v = make_float4(0.f, 0.f, 0.f, 0.f);
        int row = row0 + r;
        if (row < N) v = *(const float4*)(A + (size_t)row * C + c);
        if (MODE >= 1) {
            v.x = fmaf(v.x, g_scale[stat_in][c + 0], g_shift[stat_in][c + 0]);
            v.y = fmaf(v.y, g_scale[stat_in][c + 1], g_shift[stat_in][c + 1]);
            v.z = fmaf(v.z, g_scale[stat_in][c + 2], g_shift[stat_in][c + 2]);
            v.w = fmaf(v.w, g_scale[stat_in][c + 3], g_shift[stat_in][c + 3]);
            if (MODE == 2) {
                v.x = fmaxf(v.x, 0.f); v.y = fmaxf(v.y, 0.f);
                v.z = fmaxf(v.z, 0.f); v.w = fmaxf(v.w, 0.f);
            }
        }
        *(float4*)(sA + r * C + c) = v;
    }
    if (tid < C) { sSum[tid] = 0.f; sSq[tid] = 0.f; }
    __syncthreads();

    const int cg = tid & 31;   // col group -> cols 4*cg..4*cg+3
    const int rg = tid >> 5;   // row group -> rows 8*rg..8*rg+7

    float acc[8][4];
    #pragma unroll
    for (int r = 0; r < 8; r++)
        #pragma unroll
        for (int j = 0; j < 4; j++) acc[r][j] = 0.f;

    const float* aBase = sA + rg * 8 * C;
    const float* wBase = sW + cg * 4;

    #pragma unroll 4
    for (int k = 0; k < C; k++) {
        float4 w = *(const float4*)(wBase + k * C);
        #pragma unroll
        for (int r = 0; r < 8; r++) {
            float a = aBase[r * C + k];
            acc[r][0] = fmaf(a, w.x, acc[r][0]);
            acc[r][1] = fmaf(a, w.y, acc[r][1]);
            acc[r][2] = fmaf(a, w.z, acc[r][2]);
            acc[r][3] = fmaf(a, w.w, acc[r][3]);
        }
    }

    const int col0 = cg * 4;
    float b0 = bias[col0 + 0], b1 = bias[col0 + 1];
    float b2 = bias[col0 + 2], b3 = bias[col0 + 3];

    float ls0 = 0.f, ls1 = 0.f, ls2 = 0.f, ls3 = 0.f;
    float lq0 = 0.f, lq1 = 0.f, lq2 = 0.f, lq3 = 0.f;

    #pragma unroll
    for (int r = 0; r < 8; r++) {
        int row = row0 + rg * 8 + r;
        if (row < N) {
            float o0 = acc[r][0] + b0, o1 = acc[r][1] + b1;
            float o2 = acc[r][2] + b2, o3 = acc[r][3] + b3;
            *(float4*)(out + (size_t)row * C + col0) = make_float4(o0, o1, o2, o3);
            ls0 += o0; ls1 += o1; ls2 += o2; ls3 += o3;
            lq0 += o0 * o0; lq1 += o1 * o1; lq2 += o2 * o2; lq3 += o3 * o3;
        }
    }

    atomicAdd(&sSum[col0 + 0], ls0); atomicAdd(&sSum[col0 + 1], ls1);
    atomicAdd(&sSum[col0 + 2], ls2); atomicAdd(&sSum[col0 + 3], ls3);
    atomicAdd(&sSq[col0 + 0], lq0);  atomicAdd(&sSq[col0 + 1], lq1);
    atomicAdd(&sSq[col0 + 2], lq2);  atomicAdd(&sSq[col0 + 3], lq3);
    __syncthreads();
    if (tid < C) {
        atomicAdd(&g_sum[stat_out][tid], sSum[tid]);
        atomicAdd(&g_sq[stat_out][tid],  sSq[tid]);
    }
}

// ---------------- gather + max-pool ------------------------------------------
// pooled[n,c] = max_k ( pe[n,k,c] + relu(bn1(h0[knn[n,k],c])) )
// accumulates stats slot 1 of pooled.
__global__ void gather_kernel(const float* __restrict__ pe,
                              const int* __restrict__ knn,
                              float* __restrict__ pooled, int N) {
    const int tid  = threadIdx.x;          // 256 threads = 2 point lanes x 128 ch
    const int c    = tid & (C - 1);
    const int half = tid >> 7;             // 0 or 1
    const float sc = g_scale[0][c];
    const float sh = g_shift[0][c];

    float lsum = 0.f, lsq = 0.f;
    const int base = blockIdx.x * 64;

    #pragma unroll 1
    for (int i = 0; i < 32; i++) {
        int n = base + half + 2 * i;
        if (n < N) {
            const int*   idx   = knn + (size_t)n * KN;
            const float* peRow = pe + (size_t)n * KN * C + c;
            float m = -CUDART_INF_F;
            #pragma unroll
            for (int k = 0; k < KN; k++) {
                int j = __ldg(&idx[k]);
                float hv = fmaf(g_h0[(size_t)j * C + c], sc, sh);
                hv = fmaxf(hv, 0.f);
                m = fmaxf(m, peRow[(size_t)k * C] + hv);
            }
            pooled[(size_t)n * C + c] = m;
            lsum += m; lsq += m * m;
        }
    }
    atomicAdd(&g_sum[1][c], lsum);
    atomicAdd(&g_sq[1][c],  lsq);
}

// ---------------- residual epilogue ------------------------------------------
// out = relu(f + bn4(u)), bn4 from stats slot 3
__global__ void final_kernel(const float* __restrict__ f,
                             float* __restrict__ out, int N) {
    int i = (blockIdx.x * blockDim.x + threadIdx.x) * 4;
    if (i >= N * C) return;
    int c = i & (C - 1);
    float4 fv = *(const float4*)(f + i);
    float4 uv = *(const float4*)(g_u + i);
    float4 o;
    o.x = fmaxf(fv.x + fmaf(uv.x, g_scale[3][c + 0], g_shift[3][c + 0]), 0.f);
    o.y = fmaxf(fv.y + fmaf(uv.y, g_scale[3][c + 1], g_shift[3][c + 1]), 0.f);
    o.z = fmaxf(fv.z + fmaf(uv.z, g_scale[3][c + 2], g_shift[3][c + 2]), 0.f);
    o.w = fmaxf(fv.w + fmaf(uv.w, g_scale[3][c + 3], g_shift[3][c + 3]), 0.f);
    *(float4*)(out + i) = o;
}

// ---------------- launcher ----------------------------------------------------
extern "C" void kernel_launch(void* const* d_in, const int* in_sizes, int n_in,
                              void* d_out, int out_size) {
    // metadata order: p, f, pe, knn_index, W_pre, b_pre, g1, be1, g2, be2,
    //                 W_f1, b_f1, g3, be3, W_f2, b_f2, g4, be4
    const float* f_in  = (const float*)d_in[1];
    const float* pe    = (const float*)d_in[2];
    const int*   knn   = (const int*)  d_in[3];
    const float* W_pre = (const float*)d_in[4];
    const float* b_pre = (const float*)d_in[5];
    const float* g1    = (const float*)d_in[6];
    const float* be1   = (const float*)d_in[7];
    const float* g2    = (const float*)d_in[8];
    const float* be2   = (const float*)d_in[9];
    const float* W_f1  = (const float*)d_in[10];
    const float* b_f1  = (const float*)d_in[11];
    const float* g3    = (const float*)d_in[12];
    const float* be3   = (const float*)d_in[13];
    const float* W_f2  = (const float*)d_in[14];
    const float* b_f2  = (const float*)d_in[15];
    const float* g4    = (const float*)d_in[16];
    const float* be4   = (const float*)d_in[17];
    float* out = (float*)d_out;

    const int N = in_sizes[0] / 3;      // p is [N,3]
    const float invN = 1.0f / (float)N;

    // scratch symbol addresses
    float *p_h0, *p_pooled, *p_t, *p_u;
    cudaGetSymbolAddress((void**)&p_h0, g_h0);
    cudaGetSymbolAddress((void**)&p_pooled, g_pooled);
    cudaGetSymbolAddress((void**)&p_t, g_t);
    cudaGetSymbolAddress((void**)&p_u, g_u);

    // dynamic smem opt-in (idempotent)
    const int SMEM_GEMM = (C * C + 64 * C + 2 * C) * (int)sizeof(float); // 99,328 B
    cudaFuncSetAttribute(gemm_kernel<0>, cudaFuncAttributeMaxDynamicSharedMemorySize, SMEM_GEMM);
    cudaFuncSetAttribute(gemm_kernel<1>, cudaFuncAttributeMaxDynamicSharedMemorySize, SMEM_GEMM);
    cudaFuncSetAttribute(gemm_kernel<2>, cudaFuncAttributeMaxDynamicSharedMemorySize, SMEM_GEMM);

    const int gemmGrid   = (N + 63) / 64;
    const int gatherGrid = (N + 63) / 64;
    const int finalGrid  = (N * C / 4 + 255) / 256;

    zero_stats_kernel<<<1, 128>>>();

    // stage 1: h0 = f @ W_pre + b_pre  (stats slot 0)
    gemm_kernel<0><<<gemmGrid, 256, SMEM_GEMM>>>(f_in, W_pre, b_pre, p_h0, 0, 0, N);
    finalize_kernel<<<1, C>>>(0, g1, be1, invN);

    // stage 2: pooled = max_k(pe + relu(bn1(h0[knn])))  (stats slot 1)
    gather_kernel<<<gatherGrid, 256>>>(pe, knn, p_pooled, N);
    finalize_kernel<<<1, C>>>(1, g2, be2, invN);

    // stage 3: t = bn2(pooled) @ W_f1 + b_f1  (stats slot 2)
    gemm_kernel<1><<<gemmGrid, 256, SMEM_GEMM>>>(p_pooled, W_f1, b_f1, p_t, 1, 2, N);
    finalize_kernel<<<1, C>>>(2, g3, be3, invN);

    // stage 4: u = relu(bn3(t)) @ W_f2 + b_f2  (stats slot 3)
    gemm_kernel<2><<<gemmGrid, 256, SMEM_GEMM>>>(p_t, W_f2, b_f2, p_u, 2, 3, N);
    finalize_kernel<<<1, C>>>(3, g4, be4, invN);

    // stage 5: out = relu(f + bn4(u))
    final_kernel<<<finalGrid, 256>>>(f_in, out, N);
}